// round 6
// baseline (speedup 1.0000x reference)
#include <cuda_runtime.h>

#define HDIM 768
#define TT 4
#define TSTART 2
#define TSTOP 3
#define NB 64
#define NS1 513
#define NS 512

// Output layout (float32), tuple order:
// isqa_pred (64), crf_pred (64*512), isqa_loss (1), crf_loss (1), tags (64*512), IsQA (64)
#define OFF_ISQA_PRED 0
#define OFF_CRF_PRED  64
#define OFF_ISQA_LOSS (64 + NB*NS)          // 32832
#define OFF_CRF_LOSS  (OFF_ISQA_LOSS + 1)   // 32833
#define OFF_TAGS      (OFF_CRF_LOSS + 1)    // 32834
#define OFF_ISQA      (OFF_TAGS + NB*NS)    // 65602

#define NCHUNK 16      // 16 chunks of 32 steps per batch
#define FBLOCKS 1024   // feats blocks (32 rows each)

__device__ __align__(16) float g_feats[NB * NS * TT];  // 512 KB scratch
__device__ float g_isqa_loss[NB];
__device__ float g_zg[NB];
__device__ int   g_ctr = 0;
__device__ int   g_flag[FBLOCKS];   // zero-init; self-resetting each launch

// exact a+b issued as FFMA-imm
__device__ __forceinline__ float addx(float a, float b) {
    float r;
    asm("fma.rn.f32 %0, %1, 0f3F800000, %2;" : "=f"(r) : "f"(a), "f"(b));
    return r;
}

// tag-map composition: (a ∘ b)(t) = a[b[t]], maps stored as 4 bytes (values 0..3)
__device__ __forceinline__ unsigned cmap(unsigned a, unsigned b) {
    unsigned sel = (b & 3u) | ((b >> 4) & 0x30u) | ((b >> 8) & 0x300u) | ((b >> 12) & 0x3000u);
    return __byte_perm(a, 0, sel);
}

__device__ __forceinline__ void rescale16(float C[4][4], float& logacc) {
    float mx = C[0][0];
    #pragma unroll
    for (int i = 0; i < 4; i++)
        #pragma unroll
        for (int j = 0; j < 4; j++) mx = fmaxf(mx, C[i][j]);
    int e = (__float_as_int(mx) >> 23) & 255;
    float inv = __int_as_float((254 - e) << 23);   // exact 2^(127-e)
    logacc += (float)(e - 127) * 0.6931471805599453f;
    #pragma unroll
    for (int i = 0; i < 4; i++)
        #pragma unroll
        for (int j = 0; j < 4; j++) C[i][j] *= inv;
}

// ===========================================================================
// Fused kernel. blockIdx 0..63: CRF consumer for batch b (6 warps:
//   w0 viterbi+bp+backtrack, w1 Z, w2 CLS+gold, w3 chunk loader, w4/5 idle).
// blockIdx 64..1087: feats producer block j = blockIdx-64, rows [32j,32j+32).
// ===========================================================================
__global__ void __launch_bounds__(192, 4)
fused_kernel(const float* __restrict__ emb,
             const int* __restrict__ asl,
             const int* __restrict__ isqa,
             const float* __restrict__ fc2W,
             const float* __restrict__ fc2b,
             const float* __restrict__ crfW,
             const float* __restrict__ crfb,
             const float* __restrict__ trans,
             float* __restrict__ out)
{
    __shared__ __align__(16) float sf[NS * TT];      // 8KB feats (crf role)
    __shared__ __align__(16) float sdelta[NS * TT];  // 8KB viterbi deltas
    __shared__ float sred[2][6][4][4];               // feats role reduction
    __shared__ float sbias[4];
    __shared__ float str[16];
    __shared__ float sZ, sgold;
    __shared__ int sready;                            // chunks loaded so far
    __shared__ int sflag;

    int tid = threadIdx.x;
    int warp = tid >> 5;
    int lane = tid & 31;

    // =======================================================================
    // FEATS producer role
    // =======================================================================
    if (blockIdx.x >= 64) {
        int j = blockIdx.x - 64;
        if (tid < 4) sbias[tid] = crfb[tid];

        const float4* W4 = reinterpret_cast<const float4*>(crfW);
        float4 w0 = W4[0 * 192 + tid];
        float4 w1 = W4[1 * 192 + tid];
        float4 w2 = W4[2 * 192 + tid];
        float4 w3 = W4[3 * 192 + tid];

        int rowbase = j * 32;           // logical row = b*512 + s
        int b = rowbase >> 9;
        int s0 = rowbase & 511;

        if (tid < 32) {
            out[OFF_TAGS + rowbase + tid] = (float)asl[b * NS1 + 1 + s0 + tid];
        }

        const float4* embp = reinterpret_cast<const float4*>(emb)
                           + ((size_t)b * NS1 + 1 + s0) * 192 + tid;

        float4 v0 = embp[0 * 192];
        float4 v1 = embp[1 * 192];
        float4 v2 = embp[2 * 192];
        float4 v3 = embp[3 * 192];
        embp += 4 * 192;

        int mytag = (lane & 1) * 2 + ((lane >> 1) & 1);

        #pragma unroll 2
        for (int batch = 0; batch < 8; batch++) {
            float4 n0 = v0, n1 = v1, n2 = v2, n3 = v3;
            if (batch < 7) {
                n0 = embp[0 * 192];
                n1 = embp[1 * 192];
                n2 = embp[2 * 192];
                n3 = embp[3 * 192];
                embp += 4 * 192;
            }

            float val[4];
            #pragma unroll
            for (int r = 0; r < 4; r++) {
                float4 v = (r == 0) ? v0 : ((r == 1) ? v1 : ((r == 2) ? v2 : v3));
                float p0 = v.x * w0.x + v.y * w0.y + v.z * w0.z + v.w * w0.w;
                float p1 = v.x * w1.x + v.y * w1.y + v.z * w1.z + v.w * w1.w;
                float p2 = v.x * w2.x + v.y * w2.y + v.z * w2.z + v.w * w2.w;
                float p3 = v.x * w3.x + v.y * w3.y + v.z * w3.z + v.w * w3.w;

                float s0a = (lane & 1) ? p0 : p2;
                float s1a = (lane & 1) ? p1 : p3;
                float r0 = __shfl_xor_sync(0xffffffffu, s0a, 1);
                float r1 = __shfl_xor_sync(0xffffffffu, s1a, 1);
                float q0, q1;
                if (lane & 1) { q0 = p2 + r0; q1 = p3 + r1; }
                else          { q0 = p0 + r0; q1 = p1 + r1; }
                float sB = (lane & 2) ? q0 : q1;
                float rB = __shfl_xor_sync(0xffffffffu, sB, 2);
                float vv = ((lane & 2) ? q1 : q0) + rB;
                vv += __shfl_xor_sync(0xffffffffu, vv, 4);
                vv += __shfl_xor_sync(0xffffffffu, vv, 8);
                vv += __shfl_xor_sync(0xffffffffu, vv, 16);
                val[r] = vv;
            }

            int buf = batch & 1;
            if (lane < 4) {
                #pragma unroll
                for (int r = 0; r < 4; r++)
                    sred[buf][warp][r][mytag] = val[r];
            }
            __syncthreads();
            if (tid < 16) {
                int r = tid >> 2, t = tid & 3;
                float s = sred[buf][0][r][t] + sred[buf][1][r][t] + sred[buf][2][r][t]
                        + sred[buf][3][r][t] + sred[buf][4][r][t] + sred[buf][5][r][t]
                        + sbias[t];
                g_feats[(size_t)(rowbase + batch * 4 + r) * 4 + t] = s;
            }
            v0 = n0; v1 = n1; v2 = n2; v3 = n3;
        }

        // publish chunk j
        __syncthreads();
        if (tid == 0) {
            __threadfence();
            ((volatile int*)g_flag)[j] = 1;
        }
        return;
    }

    // =======================================================================
    // CRF consumer role: batch b = blockIdx.x
    // =======================================================================
    int b = blockIdx.x;
    float4* sf4 = reinterpret_cast<float4*>(sf);
    float4* sd4 = reinterpret_cast<float4*>(sdelta);

    if (tid < 16) str[tid] = trans[tid];
    if (tid == 0) { sflag = 0; sready = 0; }
    __syncthreads();

    volatile int* vready = &sready;

    if (warp == 3) {
        // ============ loader: stream 16 chunks g_feats -> smem ============
        const float4* gf = reinterpret_cast<const float4*>(g_feats + (size_t)b * NS * TT);
        for (int c = 0; c < NCHUNK; c++) {
            if (lane == 0) {
                while (((volatile int*)g_flag)[16 * b + c] == 0) __nanosleep(40);
            }
            __syncwarp();
            __threadfence();   // acquire: producer's g_feats writes
            sf4[c * 32 + lane] = gf[c * 32 + lane];
            __threadfence_block();
            __syncwarp();
            if (lane == 0) *vready = c + 1;
        }
    } else if (warp == 0) {
        // ===================== Viterbi =====================
        float tr[16];
        #pragma unroll
        for (int i = 0; i < 16; i++) tr[i] = str[i];

        int lt = 0;
        if (lane == 0) {
            float d0, d1, d2, d3;
            for (int c = 0; c < NCHUNK; c++) {
                while (*vready <= c) __nanosleep(30);
                __threadfence_block();
                int sA = c * 32;
                int sEnd = sA + 32;
                if (c == 0) {
                    float4 f0 = sf4[0];
                    d0 = f0.x + tr[TSTART * 4 + 0];
                    d1 = f0.y + tr[TSTART * 4 + 1];
                    d2 = f0.z + tr[TSTART * 4 + 2];
                    d3 = f0.w + tr[TSTART * 4 + 3];
                    sd4[0] = make_float4(d0, d1, d2, d3);
                    sA = 1;
                }
                #pragma unroll 4
                for (int s = sA; s < sEnd; s++) {
                    float4 f = sf4[s];
                    float a00 = addx(d0, tr[0]),  a10 = addx(d1, tr[4]),  a20 = addx(d2, tr[8]),  a30 = addx(d3, tr[12]);
                    float a01 = addx(d0, tr[1]),  a11 = addx(d1, tr[5]),  a21 = addx(d2, tr[9]),  a31 = addx(d3, tr[13]);
                    float a02 = addx(d0, tr[2]),  a12 = addx(d1, tr[6]),  a22 = addx(d2, tr[10]), a32 = addx(d3, tr[14]);
                    float a03 = addx(d0, tr[3]),  a13 = addx(d1, tr[7]),  a23 = addx(d2, tr[11]), a33 = addx(d3, tr[15]);
                    float m0 = fmaxf(fmaxf(a00, a10), fmaxf(a20, a30));
                    float m1 = fmaxf(fmaxf(a01, a11), fmaxf(a21, a31));
                    float m2 = fmaxf(fmaxf(a02, a12), fmaxf(a22, a32));
                    float m3 = fmaxf(fmaxf(a03, a13), fmaxf(a23, a33));
                    d0 = addx(m0, f.x);
                    d1 = addx(m1, f.y);
                    d2 = addx(m2, f.z);
                    d3 = addx(m3, f.w);
                    sd4[s] = make_float4(d0, d1, d2, d3);
                }
            }
            float w0v = d0 + tr[0 * 4 + TSTOP];
            float w1v = d1 + tr[1 * 4 + TSTOP];
            float w2v = d2 + tr[2 * 4 + TSTOP];
            float w3v = d3 + tr[3 * 4 + TSTOP];
            float mm = fmaxf(fmaxf(w0v, w1v), fmaxf(w2v, w3v));
            lt = (w0v == mm) ? 0 : ((w1v == mm) ? 1 : ((w2v == mm) ? 2 : 3));
        }
        __syncwarp();
        lt = __shfl_sync(0xffffffffu, lt, 0);

        // ---- parallel backpointer recompute: lane l -> steps [16l, 16l+15] ----
        unsigned mp[16];
        mp[0] = 0x03020100u;
        int sbase = lane * 16;
        #pragma unroll
        for (int k = 0; k < 16; k++) {
            int s = sbase + k;
            if (s >= 1) {
                float4 dp = sd4[s - 1];
                unsigned m = 0;
                #pragma unroll
                for (int j = 0; j < 4; j++) {
                    float w0v = dp.x + tr[0 * 4 + j];
                    float w1v = dp.y + tr[1 * 4 + j];
                    float w2v = dp.z + tr[2 * 4 + j];
                    float w3v = dp.w + tr[3 * 4 + j];
                    float mm = fmaxf(fmaxf(w0v, w1v), fmaxf(w2v, w3v));
                    unsigned bi = (w0v == mm) ? 0u : ((w1v == mm) ? 1u : ((w2v == mm) ? 2u : 3u));
                    m |= bi << (8 * j);
                }
                mp[k] = m;
            }
        }

        unsigned G = mp[15];
        #pragma unroll
        for (int k = 14; k >= 0; k--) G = cmap(mp[k], G);

        unsigned T = G;
        #pragma unroll
        for (int off = 1; off < 32; off <<= 1) {
            unsigned g2 = __shfl_down_sync(0xffffffffu, T, off);
            if (lane + off < 32) T = cmap(T, g2);
        }
        unsigned S = __shfl_down_sync(0xffffffffu, T, 1);
        if (lane == 31) S = 0x03020100u;

        unsigned t = (S >> (8 * (unsigned)lt)) & 3u;
        float* outp = out + OFF_CRF_PRED + b * NS + sbase;
        outp[15] = (float)t;
        #pragma unroll
        for (int k = 15; k >= 1; k--) {
            t = (mp[k] >> (8 * t)) & 3u;
            outp[k - 1] = (float)t;
        }
    } else if (warp == 1) {
        // ===================== Z (linear domain) =====================
        float tr[16], etr[16];
        #pragma unroll
        for (int i = 0; i < 16; i++) { tr[i] = str[i]; etr[i] = __expf(str[i]); }

        while (*vready < NCHUNK) __nanosleep(60);
        __threadfence_block();

        float C[4][4];
        float logacc = 0.f;
        int sbase = lane * 16;
        {
            float4 f = sf4[sbase];
            float e0 = __expf(f.x), e1 = __expf(f.y), e2 = __expf(f.z), e3 = __expf(f.w);
            if (lane == 0) {
                float b0 = __expf(tr[TSTART * 4 + 0]) * e0;
                float b1 = __expf(tr[TSTART * 4 + 1]) * e1;
                float b2 = __expf(tr[TSTART * 4 + 2]) * e2;
                float b3 = __expf(tr[TSTART * 4 + 3]) * e3;
                #pragma unroll
                for (int i = 0; i < 4; i++) { C[i][0] = b0; C[i][1] = b1; C[i][2] = b2; C[i][3] = b3; }
            } else {
                #pragma unroll
                for (int i = 0; i < 4; i++) {
                    C[i][0] = etr[i * 4 + 0] * e0;
                    C[i][1] = etr[i * 4 + 1] * e1;
                    C[i][2] = etr[i * 4 + 2] * e2;
                    C[i][3] = etr[i * 4 + 3] * e3;
                }
            }
        }
        #pragma unroll
        for (int k = 1; k < 16; k++) {
            float4 f = sf4[sbase + k];
            float e0 = __expf(f.x), e1 = __expf(f.y), e2 = __expf(f.z), e3 = __expf(f.w);
            #pragma unroll
            for (int i = 0; i < 4; i++) {
                float t0 = C[i][0] * etr[0] + C[i][1] * etr[4] + C[i][2] * etr[8]  + C[i][3] * etr[12];
                float t1 = C[i][0] * etr[1] + C[i][1] * etr[5] + C[i][2] * etr[9]  + C[i][3] * etr[13];
                float t2 = C[i][0] * etr[2] + C[i][1] * etr[6] + C[i][2] * etr[10] + C[i][3] * etr[14];
                float t3 = C[i][0] * etr[3] + C[i][1] * etr[7] + C[i][2] * etr[11] + C[i][3] * etr[15];
                C[i][0] = t0 * e0; C[i][1] = t1 * e1; C[i][2] = t2 * e2; C[i][3] = t3 * e3;
            }
            if ((k & 7) == 7) rescale16(C, logacc);
        }

        #pragma unroll
        for (int off = 1; off < 32; off <<= 1) {
            float R[4][4];
            #pragma unroll
            for (int i = 0; i < 4; i++)
                #pragma unroll
                for (int j = 0; j < 4; j++)
                    R[i][j] = __shfl_down_sync(0xffffffffu, C[i][j], off);
            float lg2 = __shfl_down_sync(0xffffffffu, logacc, off);
            if ((lane & (2 * off - 1)) == 0) {
                float Tm[4][4];
                #pragma unroll
                for (int i = 0; i < 4; i++)
                    #pragma unroll
                    for (int j = 0; j < 4; j++)
                        Tm[i][j] = C[i][0] * R[0][j] + C[i][1] * R[1][j]
                                 + C[i][2] * R[2][j] + C[i][3] * R[3][j];
                #pragma unroll
                for (int i = 0; i < 4; i++)
                    #pragma unroll
                    for (int j = 0; j < 4; j++) C[i][j] = Tm[i][j];
                logacc += lg2;
                rescale16(C, logacc);
            }
        }

        if (lane == 0) {
            float z0 = C[0][0] * etr[0 * 4 + TSTOP] + C[0][1] * etr[1 * 4 + TSTOP]
                     + C[0][2] * etr[2 * 4 + TSTOP] + C[0][3] * etr[3 * 4 + TSTOP];
            sZ = logacc + __logf(z0);
        }
    } else if (warp == 2) {
        // ============ CLS / isqa head (independent of feats) ============
        const float4* crow = reinterpret_cast<const float4*>(emb) + (size_t)b * NS1 * 192;
        const float4* f2 = reinterpret_cast<const float4*>(fc2W);
        float a0 = 0.f, a1 = 0.f;
        #pragma unroll
        for (int j = 0; j < 6; j++) {
            int c = lane + 32 * j;
            float4 v = crow[c];
            float4 u0 = f2[c];
            float4 u1 = f2[192 + c];
            a0 += v.x * u0.x + v.y * u0.y + v.z * u0.z + v.w * u0.w;
            a1 += v.x * u1.x + v.y * u1.y + v.z * u1.z + v.w * u1.w;
        }
        #pragma unroll
        for (int o = 16; o; o >>= 1) {
            a0 += __shfl_xor_sync(0xffffffffu, a0, o);
            a1 += __shfl_xor_sync(0xffffffffu, a1, o);
        }
        if (lane == 0) {
            float l0 = a0 + fc2b[0];
            float l1 = a1 + fc2b[1];
            int pred = (l1 > l0) ? 1 : 0;
            float m = fmaxf(l0, l1);
            float lse = m + __logf(__expf(l0 - m) + __expf(l1 - m));
            int q = isqa[b];
            out[OFF_ISQA_PRED + b] = (float)pred;
            out[OFF_ISQA + b] = (float)q;
            g_isqa_loss[b] = lse - (q ? l1 : l0);
        }

        // ============ gold score (streamed per chunk) ============
        const int* tagp = asl + b * NS1 + 1;
        float partial = 0.f;
        for (int c = 0; c < NCHUNK; c++) {
            while (*vready <= c) __nanosleep(30);
            __threadfence_block();
            int s = c * 32 + lane;
            int tg = tagp[s];
            partial += sf[s * 4 + tg];
            if (s < NS - 1) partial += str[tg * 4 + tagp[s + 1]];
        }
        #pragma unroll
        for (int o = 16; o; o >>= 1) partial += __shfl_xor_sync(0xffffffffu, partial, o);
        if (lane == 0) {
            sgold = partial + str[TSTART * 4 + tagp[0]] + str[tagp[NS - 1] * 4 + TSTOP];
        }
    }
    // warps 4,5: nothing

    // ===================== combine, loss ticket, flag reset =====================
    __syncthreads();
    if (tid == 0) {
        g_zg[b] = sZ - sgold;
        __threadfence();
        int t = atomicAdd(&g_ctr, 1);
        sflag = (t == NB - 1) ? 1 : 0;
    }
    __syncthreads();
    if (sflag) {
        __threadfence();
        if (tid < 32) {
            float v1 = g_isqa_loss[tid] + g_isqa_loss[tid + 32];
            float v2 = g_zg[tid] + g_zg[tid + 32];
            #pragma unroll
            for (int o = 16; o; o >>= 1) {
                v1 += __shfl_xor_sync(0xffffffffu, v1, o);
                v2 += __shfl_xor_sync(0xffffffffu, v2, o);
            }
            if (tid == 0) {
                out[OFF_ISQA_LOSS] = v1 * (1.0f / NB);
                out[OFF_CRF_LOSS]  = v2 * (1.0f / NB);
                g_ctr = 0;  // reset for next graph replay
            }
        }
    }
    // reset this batch's flags for the next replay
    if (tid < NCHUNK) g_flag[16 * b + tid] = 0;
}

extern "C" void kernel_launch(void* const* d_in, const int* in_sizes, int n_in,
                              void* d_out, int out_size)
{
    const float* emb   = (const float*)d_in[0];
    const int*   asl   = (const int*)d_in[1];
    const int*   isqa  = (const int*)d_in[2];
    const float* fc2W  = (const float*)d_in[3];
    const float* fc2b  = (const float*)d_in[4];
    const float* crfW  = (const float*)d_in[5];
    const float* crfb  = (const float*)d_in[6];
    const float* trans = (const float*)d_in[7];
    float* out = (float*)d_out;

    fused_kernel<<<64 + FBLOCKS, 192>>>(emb, asl, isqa, fc2W, fc2b, crfW, crfb, trans, out);
}

// round 8
// speedup vs baseline: 1.3035x; 1.3035x over previous
#include <cuda_runtime.h>

#define HDIM 768
#define TT 4
#define TSTART 2
#define TSTOP 3
#define NB 64
#define NS1 513
#define NS 512

// Output layout (float32), tuple order:
// isqa_pred (64), crf_pred (64*512), isqa_loss (1), crf_loss (1), tags (64*512), IsQA (64)
#define OFF_ISQA_PRED 0
#define OFF_CRF_PRED  64
#define OFF_ISQA_LOSS (64 + NB*NS)          // 32832
#define OFF_CRF_LOSS  (OFF_ISQA_LOSS + 1)   // 32833
#define OFF_TAGS      (OFF_CRF_LOSS + 1)    // 32834
#define OFF_ISQA      (OFF_TAGS + NB*NS)    // 65602

__device__ __align__(16) float g_feats[NB * NS * TT];  // 512 KB scratch
__device__ float g_isqa_loss[NB];
__device__ float g_zg[NB];
__device__ int   g_ctr = 0;

// exact a+b issued as FFMA-imm
__device__ __forceinline__ float addx(float a, float b) {
    float r;
    asm("fma.rn.f32 %0, %1, 0f3F800000, %2;" : "=f"(r) : "f"(a), "f"(b));
    return r;
}

// one exact Viterbi step (must stay bit-identical everywhere it is used)
__device__ __forceinline__ void vstep(float& d0, float& d1, float& d2, float& d3,
                                      const float tr[16], float4 f) {
    float a00 = addx(d0, tr[0]),  a10 = addx(d1, tr[4]),  a20 = addx(d2, tr[8]),  a30 = addx(d3, tr[12]);
    float a01 = addx(d0, tr[1]),  a11 = addx(d1, tr[5]),  a21 = addx(d2, tr[9]),  a31 = addx(d3, tr[13]);
    float a02 = addx(d0, tr[2]),  a12 = addx(d1, tr[6]),  a22 = addx(d2, tr[10]), a32 = addx(d3, tr[14]);
    float a03 = addx(d0, tr[3]),  a13 = addx(d1, tr[7]),  a23 = addx(d2, tr[11]), a33 = addx(d3, tr[15]);
    float m0 = fmaxf(fmaxf(a00, a10), fmaxf(a20, a30));
    float m1 = fmaxf(fmaxf(a01, a11), fmaxf(a21, a31));
    float m2 = fmaxf(fmaxf(a02, a12), fmaxf(a22, a32));
    float m3 = fmaxf(fmaxf(a03, a13), fmaxf(a23, a33));
    d0 = addx(m0, f.x);
    d1 = addx(m1, f.y);
    d2 = addx(m2, f.z);
    d3 = addx(m3, f.w);
}

// same step, also extracting packed backpointers (identical arithmetic)
__device__ __forceinline__ unsigned bpstep(float& d0, float& d1, float& d2, float& d3,
                                           const float tr[16], float4 f) {
    float fv[4] = {f.x, f.y, f.z, f.w};
    float nd[4];
    unsigned m = 0;
    #pragma unroll
    for (int j = 0; j < 4; j++) {
        float a0 = addx(d0, tr[0 * 4 + j]);
        float a1 = addx(d1, tr[1 * 4 + j]);
        float a2 = addx(d2, tr[2 * 4 + j]);
        float a3 = addx(d3, tr[3 * 4 + j]);
        float mm = fmaxf(fmaxf(a0, a1), fmaxf(a2, a3));
        unsigned bi = (a0 == mm) ? 0u : ((a1 == mm) ? 1u : ((a2 == mm) ? 2u : 3u));
        m |= bi << (8 * j);
        nd[j] = addx(mm, fv[j]);
    }
    d0 = nd[0]; d1 = nd[1]; d2 = nd[2]; d3 = nd[3];
    return m;
}

// tag-map composition: (a ∘ b)(t) = a[b[t]], maps stored as 4 bytes (values 0..3)
__device__ __forceinline__ unsigned cmap(unsigned a, unsigned b) {
    unsigned sel = (b & 3u) | ((b >> 4) & 0x30u) | ((b >> 8) & 0x300u) | ((b >> 12) & 0x3000u);
    return __byte_perm(a, 0, sel);
}

__device__ __forceinline__ void rescale16(float C[4][4], float& logacc) {
    float mx = C[0][0];
    #pragma unroll
    for (int i = 0; i < 4; i++)
        #pragma unroll
        for (int j = 0; j < 4; j++) mx = fmaxf(mx, C[i][j]);
    int e = (__float_as_int(mx) >> 23) & 255;
    float inv = __int_as_float((254 - e) << 23);   // exact 2^(127-e)
    logacc += (float)(e - 127) * 0.6931471805599453f;
    #pragma unroll
    for (int i = 0; i < 4; i++)
        #pragma unroll
        for (int j = 0; j < 4; j++) C[i][j] *= inv;
}

// ---------------------------------------------------------------------------
// Kernel A: feats GEMV, thread-owns-column layout (round-5, unchanged).
// ---------------------------------------------------------------------------
__global__ void __launch_bounds__(192, 4)
feats_kernel(const float* __restrict__ emb,
             const int* __restrict__ asl,
             const float* __restrict__ crfW,
             const float* __restrict__ crfb,
             float* __restrict__ out)
{
    __shared__ float sred[2][6][4][4];
    __shared__ float sbias[4];

    int tid = threadIdx.x;
    int warp = tid >> 5;
    int lane = tid & 31;
    if (tid < 4) sbias[tid] = crfb[tid];

    const float4* W4 = reinterpret_cast<const float4*>(crfW);
    float4 w0 = W4[0 * 192 + tid];
    float4 w1 = W4[1 * 192 + tid];
    float4 w2 = W4[2 * 192 + tid];
    float4 w3 = W4[3 * 192 + tid];

    int rowbase = blockIdx.x * 32;
    int b = rowbase >> 9;
    int s0 = rowbase & 511;

    if (tid < 32) {
        out[OFF_TAGS + rowbase + tid] = (float)asl[b * NS1 + 1 + s0 + tid];
    }

    const float4* embp = reinterpret_cast<const float4*>(emb)
                       + ((size_t)b * NS1 + 1 + s0) * 192 + tid;

    float4 v0 = embp[0 * 192];
    float4 v1 = embp[1 * 192];
    float4 v2 = embp[2 * 192];
    float4 v3 = embp[3 * 192];
    embp += 4 * 192;

    int mytag = (lane & 1) * 2 + ((lane >> 1) & 1);

    #pragma unroll 2
    for (int batch = 0; batch < 8; batch++) {
        float4 n0 = v0, n1 = v1, n2 = v2, n3 = v3;
        if (batch < 7) {
            n0 = embp[0 * 192];
            n1 = embp[1 * 192];
            n2 = embp[2 * 192];
            n3 = embp[3 * 192];
            embp += 4 * 192;
        }

        float val[4];
        #pragma unroll
        for (int r = 0; r < 4; r++) {
            float4 v = (r == 0) ? v0 : ((r == 1) ? v1 : ((r == 2) ? v2 : v3));
            float p0 = v.x * w0.x + v.y * w0.y + v.z * w0.z + v.w * w0.w;
            float p1 = v.x * w1.x + v.y * w1.y + v.z * w1.z + v.w * w1.w;
            float p2 = v.x * w2.x + v.y * w2.y + v.z * w2.z + v.w * w2.w;
            float p3 = v.x * w3.x + v.y * w3.y + v.z * w3.z + v.w * w3.w;

            float s0a = (lane & 1) ? p0 : p2;
            float s1a = (lane & 1) ? p1 : p3;
            float r0 = __shfl_xor_sync(0xffffffffu, s0a, 1);
            float r1 = __shfl_xor_sync(0xffffffffu, s1a, 1);
            float q0, q1;
            if (lane & 1) { q0 = p2 + r0; q1 = p3 + r1; }
            else          { q0 = p0 + r0; q1 = p1 + r1; }
            float sB = (lane & 2) ? q0 : q1;
            float rB = __shfl_xor_sync(0xffffffffu, sB, 2);
            float vv = ((lane & 2) ? q1 : q0) + rB;
            vv += __shfl_xor_sync(0xffffffffu, vv, 4);
            vv += __shfl_xor_sync(0xffffffffu, vv, 8);
            vv += __shfl_xor_sync(0xffffffffu, vv, 16);
            val[r] = vv;
        }

        int buf = batch & 1;
        if (lane < 4) {
            #pragma unroll
            for (int r = 0; r < 4; r++)
                sred[buf][warp][r][mytag] = val[r];
        }
        __syncthreads();
        if (tid < 16) {
            int r = tid >> 2, t = tid & 3;
            float s = sred[buf][0][r][t] + sred[buf][1][r][t] + sred[buf][2][r][t]
                    + sred[buf][3][r][t] + sred[buf][4][r][t] + sred[buf][5][r][t]
                    + sbias[t];
            g_feats[(size_t)(rowbase + batch * 4 + r) * 4 + t] = s;
        }
        v0 = n0; v1 = n1; v2 = n2; v3 = n3;
    }
}

// ---------------------------------------------------------------------------
// Kernel B: per-batch CRF. No staging barrier; warps stream g_feats via LDG.
// warp0: chain (reg prefetch, checkpoint every 16) + bp recompute + backtrack.
// warp1: linear-domain Z. warp2: CLS/isqa + gold. Last block: losses.
// ---------------------------------------------------------------------------
__global__ void __launch_bounds__(96)
crf_kernel(const float* __restrict__ emb,
           const int* __restrict__ asl,
           const int* __restrict__ isqa,
           const float* __restrict__ fc2W,
           const float* __restrict__ fc2b,
           const float* __restrict__ trans,
           float* __restrict__ out)
{
    __shared__ __align__(16) float4 scp[32];   // checkpoints: delta after s=16l-1
    __shared__ float str[16];                  // for gold's dynamic indexing
    __shared__ float sZ, sgold;
    __shared__ int sflag;

    int b = blockIdx.x;
    int tid = threadIdx.x;
    int lane = tid & 31;
    int w = tid >> 5;

    const float4* gfb = reinterpret_cast<const float4*>(g_feats) + (size_t)b * NS;

    if (w == 0) {
        // ===================== Viterbi chain =====================
        float tr[16];
        #pragma unroll
        for (int i = 0; i < 16; i++) tr[i] = __ldg(trans + i);

        int lt = 0;
        if (lane == 0) {
            float4 buf[8], nbuf[8];
            #pragma unroll
            for (int u = 0; u < 8; u++) buf[u] = __ldg(gfb + u);

            float d0, d1, d2, d3;
            {
                float4 f0 = buf[0];
                d0 = f0.x + tr[TSTART * 4 + 0];
                d1 = f0.y + tr[TSTART * 4 + 1];
                d2 = f0.z + tr[TSTART * 4 + 2];
                d3 = f0.w + tr[TSTART * 4 + 3];
            }

            for (int g = 0; g < 64; g++) {
                if (g < 63) {
                    #pragma unroll
                    for (int u = 0; u < 8; u++) nbuf[u] = __ldg(gfb + (g + 1) * 8 + u);
                }
                #pragma unroll
                for (int u = 0; u < 8; u++) {
                    if (g == 0 && u == 0) continue;  // init consumed buf[0]
                    vstep(d0, d1, d2, d3, tr, buf[u]);
                }
                // checkpoint after s = 8g+7 when (8g+7) % 16 == 15 (g odd), l-1 = (g-1)/2
                if ((g & 1) && g < 63) scp[(g - 1) >> 1] = make_float4(d0, d1, d2, d3);
                #pragma unroll
                for (int u = 0; u < 8; u++) buf[u] = nbuf[u];
            }

            float w0v = d0 + tr[0 * 4 + TSTOP];
            float w1v = d1 + tr[1 * 4 + TSTOP];
            float w2v = d2 + tr[2 * 4 + TSTOP];
            float w3v = d3 + tr[3 * 4 + TSTOP];
            float mm = fmaxf(fmaxf(w0v, w1v), fmaxf(w2v, w3v));
            lt = (w0v == mm) ? 0 : ((w1v == mm) ? 1 : ((w2v == mm) ? 2 : 3));
        }
        __syncwarp();
        lt = __shfl_sync(0xffffffffu, lt, 0);

        // ---- bp recompute: lane l replays steps [16l, 16l+15] from checkpoint ----
        unsigned mp[16];
        int sb = lane * 16;
        float dd0, dd1, dd2, dd3;
        if (lane == 0) {
            float4 f0 = __ldg(gfb + 0);
            dd0 = f0.x + tr[TSTART * 4 + 0];
            dd1 = f0.y + tr[TSTART * 4 + 1];
            dd2 = f0.z + tr[TSTART * 4 + 2];
            dd3 = f0.w + tr[TSTART * 4 + 3];
            mp[0] = 0x03020100u;
        } else {
            float4 c = scp[lane - 1];
            dd0 = c.x; dd1 = c.y; dd2 = c.z; dd3 = c.w;
            mp[0] = bpstep(dd0, dd1, dd2, dd3, tr, __ldg(gfb + sb));
        }
        #pragma unroll
        for (int k = 1; k < 16; k++) {
            mp[k] = bpstep(dd0, dd1, dd2, dd3, tr, __ldg(gfb + sb + k));
        }

        // segment map G_l = mp[0] ∘ ... ∘ mp[15], suffix scan, backtrack
        unsigned G = mp[15];
        #pragma unroll
        for (int k = 14; k >= 0; k--) G = cmap(mp[k], G);

        unsigned T = G;
        #pragma unroll
        for (int off = 1; off < 32; off <<= 1) {
            unsigned g2 = __shfl_down_sync(0xffffffffu, T, off);
            if (lane + off < 32) T = cmap(T, g2);
        }
        unsigned S = __shfl_down_sync(0xffffffffu, T, 1);
        if (lane == 31) S = 0x03020100u;

        unsigned t = (S >> (8 * (unsigned)lt)) & 3u;
        float* outp = out + OFF_CRF_PRED + b * NS + sb;
        outp[15] = (float)t;
        #pragma unroll
        for (int k = 15; k >= 1; k--) {
            t = (mp[k] >> (8 * t)) & 3u;
            outp[k - 1] = (float)t;
        }
    } else if (w == 1) {
        // ===================== Z (linear domain) =====================
        float tr[16], etr[16];
        #pragma unroll
        for (int i = 0; i < 16; i++) { tr[i] = __ldg(trans + i); etr[i] = __expf(tr[i]); }

        float C[4][4];
        float logacc = 0.f;
        int sbase = lane * 16;
        {
            float4 f = __ldg(gfb + sbase);
            float e0 = __expf(f.x), e1 = __expf(f.y), e2 = __expf(f.z), e3 = __expf(f.w);
            if (lane == 0) {
                float b0 = __expf(tr[TSTART * 4 + 0]) * e0;
                float b1 = __expf(tr[TSTART * 4 + 1]) * e1;
                float b2 = __expf(tr[TSTART * 4 + 2]) * e2;
                float b3 = __expf(tr[TSTART * 4 + 3]) * e3;
                #pragma unroll
                for (int i = 0; i < 4; i++) { C[i][0] = b0; C[i][1] = b1; C[i][2] = b2; C[i][3] = b3; }
            } else {
                #pragma unroll
                for (int i = 0; i < 4; i++) {
                    C[i][0] = etr[i * 4 + 0] * e0;
                    C[i][1] = etr[i * 4 + 1] * e1;
                    C[i][2] = etr[i * 4 + 2] * e2;
                    C[i][3] = etr[i * 4 + 3] * e3;
                }
            }
        }
        #pragma unroll
        for (int k = 1; k < 16; k++) {
            float4 f = __ldg(gfb + sbase + k);
            float e0 = __expf(f.x), e1 = __expf(f.y), e2 = __expf(f.z), e3 = __expf(f.w);
            #pragma unroll
            for (int i = 0; i < 4; i++) {
                float t0 = C[i][0] * etr[0] + C[i][1] * etr[4] + C[i][2] * etr[8]  + C[i][3] * etr[12];
                float t1 = C[i][0] * etr[1] + C[i][1] * etr[5] + C[i][2] * etr[9]  + C[i][3] * etr[13];
                float t2 = C[i][0] * etr[2] + C[i][1] * etr[6] + C[i][2] * etr[10] + C[i][3] * etr[14];
                float t3 = C[i][0] * etr[3] + C[i][1] * etr[7] + C[i][2] * etr[11] + C[i][3] * etr[15];
                C[i][0] = t0 * e0; C[i][1] = t1 * e1; C[i][2] = t2 * e2; C[i][3] = t3 * e3;
            }
            if ((k & 7) == 7) rescale16(C, logacc);
        }

        #pragma unroll
        for (int off = 1; off < 32; off <<= 1) {
            float R[4][4];
            #pragma unroll
            for (int i = 0; i < 4; i++)
                #pragma unroll
                for (int j = 0; j < 4; j++)
                    R[i][j] = __shfl_down_sync(0xffffffffu, C[i][j], off);
            float lg2 = __shfl_down_sync(0xffffffffu, logacc, off);
            if ((lane & (2 * off - 1)) == 0) {
                float Tm[4][4];
                #pragma unroll
                for (int i = 0; i < 4; i++)
                    #pragma unroll
                    for (int j = 0; j < 4; j++)
                        Tm[i][j] = C[i][0] * R[0][j] + C[i][1] * R[1][j]
                                 + C[i][2] * R[2][j] + C[i][3] * R[3][j];
                #pragma unroll
                for (int i = 0; i < 4; i++)
                    #pragma unroll
                    for (int j = 0; j < 4; j++) C[i][j] = Tm[i][j];
                logacc += lg2;
                rescale16(C, logacc);
            }
        }

        if (lane == 0) {
            float z0 = C[0][0] * etr[0 * 4 + TSTOP] + C[0][1] * etr[1 * 4 + TSTOP]
                     + C[0][2] * etr[2 * 4 + TSTOP] + C[0][3] * etr[3 * 4 + TSTOP];
            sZ = logacc + __logf(z0);
        }
    } else {
        // ===================== CLS / isqa + gold =====================
        if (lane < 16) str[lane] = __ldg(trans + lane);
        __syncwarp();

        const float4* crow = reinterpret_cast<const float4*>(emb) + (size_t)b * NS1 * 192;
        const float4* f2 = reinterpret_cast<const float4*>(fc2W);
        float a0 = 0.f, a1 = 0.f;
        #pragma unroll
        for (int j = 0; j < 6; j++) {
            int c = lane + 32 * j;
            float4 v = crow[c];
            float4 u0 = f2[c];
            float4 u1 = f2[192 + c];
            a0 += v.x * u0.x + v.y * u0.y + v.z * u0.z + v.w * u0.w;
            a1 += v.x * u1.x + v.y * u1.y + v.z * u1.z + v.w * u1.w;
        }
        #pragma unroll
        for (int o = 16; o; o >>= 1) {
            a0 += __shfl_xor_sync(0xffffffffu, a0, o);
            a1 += __shfl_xor_sync(0xffffffffu, a1, o);
        }
        if (lane == 0) {
            float l0 = a0 + fc2b[0];
            float l1 = a1 + fc2b[1];
            int pred = (l1 > l0) ? 1 : 0;
            float m = fmaxf(l0, l1);
            float lse = m + __logf(__expf(l0 - m) + __expf(l1 - m));
            int q = isqa[b];
            out[OFF_ISQA_PRED + b] = (float)pred;
            out[OFF_ISQA + b] = (float)q;
            g_isqa_loss[b] = lse - (q ? l1 : l0);
        }

        // gold score
        const int* tagp = asl + b * NS1 + 1;
        const float* gff = g_feats + (size_t)b * NS * TT;
        float partial = 0.f;
        for (int s = lane; s < NS; s += 32) {
            int tg = tagp[s];
            partial += __ldg(gff + s * 4 + tg);
            if (s < NS - 1) partial += str[tg * 4 + tagp[s + 1]];
        }
        #pragma unroll
        for (int o = 16; o; o >>= 1) partial += __shfl_xor_sync(0xffffffffu, partial, o);
        if (lane == 0) {
            sgold = partial + str[TSTART * 4 + tagp[0]] + str[tagp[NS - 1] * 4 + TSTOP];
        }
    }

    // ===================== combine + loss ticket =====================
    __syncthreads();
    if (tid == 0) {
        g_zg[b] = sZ - sgold;
        __threadfence();
        int t = atomicAdd(&g_ctr, 1);
        sflag = (t == NB - 1) ? 1 : 0;
    }
    __syncthreads();
    if (sflag) {
        __threadfence();
        if (tid < 32) {
            float v1 = g_isqa_loss[tid] + g_isqa_loss[tid + 32];
            float v2 = g_zg[tid] + g_zg[tid + 32];
            #pragma unroll
            for (int o = 16; o; o >>= 1) {
                v1 += __shfl_xor_sync(0xffffffffu, v1, o);
                v2 += __shfl_xor_sync(0xffffffffu, v2, o);
            }
            if (tid == 0) {
                out[OFF_ISQA_LOSS] = v1 * (1.0f / NB);
                out[OFF_CRF_LOSS]  = v2 * (1.0f / NB);
                g_ctr = 0;  // reset for next graph replay
            }
        }
    }
}

extern "C" void kernel_launch(void* const* d_in, const int* in_sizes, int n_in,
                              void* d_out, int out_size)
{
    const float* emb   = (const float*)d_in[0];
    const int*   asl   = (const int*)d_in[1];
    const int*   isqa  = (const int*)d_in[2];
    const float* fc2W  = (const float*)d_in[3];
    const float* fc2b  = (const float*)d_in[4];
    const float* crfW  = (const float*)d_in[5];
    const float* crfb  = (const float*)d_in[6];
    const float* trans = (const float*)d_in[7];
    float* out = (float*)d_out;

    feats_kernel<<<1024, 192>>>(emb, asl, crfW, crfb, out);
    crf_kernel<<<NB, 96>>>(emb, asl, isqa, fc2W, fc2b, trans, out);
}